// round 3
// baseline (speedup 1.0000x reference)
#include <cuda_runtime.h>
#include <cuda_bf16.h>
#include <math.h>

// SimilarityLoss: out = mean(pos) + mean(clip(MARGIN - kth-smallest-dist, 0))
// Structure:
//   init     : zero g_neg
//   norms    : per-row sq norms of o1/o2 + positive loss per row
//   screen   : fp32 register-blocked "GEMM" (packed fma.rn.f32x2, register-
//              prefetch double buffering) computing per-row min d2 (no topk)
//   exact    : for rows with min d2 < 4.5 (i.e. possibly dist < MARGIN=2),
//              exact sorted top-quant selection with jax-top_k tie-breaking
//   finalize : deterministic fixed-order reduction -> scalar
//
// Determinism: no float atomics anywhere; every reduction is fixed-order.

#define NROWS 8192
#define DDIM  64
#define TR    128          // row tile
#define TC    128          // col tile
#define NCTA_COL 2         // column split -> 64*2 = 128 CTAs
#define COLS_PER (NROWS / NCTA_COL)
#define NTILES   (COLS_PER / TC)
#define THRESH   4.5f      // screen threshold on d2 (exact boundary is 4.0)
#define MARGIN_V 2.0f

__device__ float g_sq1[NROWS];
__device__ float g_sq2[NROWS];
__device__ float g_pos[NROWS];
__device__ float g_neg[NROWS];
__device__ float g_minpart[NCTA_COL][NROWS];
__device__ unsigned long long g_scratch[64][NROWS];  // exact-path keys (4MB)

// ---------------------------------------------------------------- init
__global__ void init_kernel() {
    int i = blockIdx.x * blockDim.x + threadIdx.x;
    if (i < NROWS) g_neg[i] = 0.0f;
}

// ---------------------------------------------------------------- norms + pos
__global__ void norms_kernel(const float* __restrict__ o1,
                             const float* __restrict__ o2) {
    int warp = threadIdx.x >> 5;
    int lane = threadIdx.x & 31;
    int row = blockIdx.x * 8 + warp;
    if (row >= NROWS) return;
    const float* a = o1 + row * DDIM;
    const float* b = o2 + row * DDIM;
    float a0 = a[lane], a1 = a[lane + 32];
    float b0 = b[lane], b1 = b[lane + 32];
    float s1 = a0 * a0 + a1 * a1;
    float s2 = b0 * b0 + b1 * b1;
    float d0 = b0 - a0, d1 = b1 - a1;
    float pp = d0 * d0 + d1 * d1;
    #pragma unroll
    for (int off = 16; off > 0; off >>= 1) {
        s1 += __shfl_xor_sync(0xffffffffu, s1, off);
        s2 += __shfl_xor_sync(0xffffffffu, s2, off);
        pp += __shfl_xor_sync(0xffffffffu, pp, off);
    }
    if (lane == 0) {
        g_sq1[row] = s1;
        g_sq2[row] = s2;
        g_pos[row] = pp;
    }
}

// ---------------------------------------------------------------- screen GEMM
// grid (64, 2), block 256. Each CTA: 128 rows x 4096 cols, K=64.
// smem tiles k-major with XOR swizzle: index = k*128 + (r ^ (((k>>2)&7)<<2)).
// Inner product uses packed fma.rn.f32x2 (column-pair accumulators; B pairs
// load as 64-bit from smem, swizzle preserves pair adjacency; A broadcast via
// mov.b64 {a,a}). Next B tile is prefetched into registers BEFORE the compute
// loop so LDG latency overlaps the 64 k-iterations.
__global__ void __launch_bounds__(256, 1)
screen_kernel(const float* __restrict__ o1, const float* __restrict__ o2) {
    __shared__ float As[DDIM * TR];
    __shared__ float Bs[DDIM * TC];
    __shared__ float sq1s[TR];
    __shared__ float sq2s[TC];

    int tid = threadIdx.x;
    int tx = tid & 15;        // 16 col groups of 8
    int ty = tid >> 4;        // 16 row groups of 8
    int row0 = blockIdx.x * TR;
    int cb = blockIdx.y;

    // load A tile once (transpose to k-major with swizzle)
    const float4* o1v = (const float4*)o1;
    #pragma unroll
    for (int i = 0; i < 8; i++) {
        int idx = tid + i * 256;          // 0..2047
        int q = idx & 15;                 // float4 index along D
        int r = idx >> 4;                 // row within tile
        float4 v = o1v[(row0 + r) * (DDIM / 4) + q];
        int k = q * 4;
        int rs = r ^ ((q & 7) << 2);
        As[(k + 0) * TR + rs] = v.x;
        As[(k + 1) * TR + rs] = v.y;
        As[(k + 2) * TR + rs] = v.z;
        As[(k + 3) * TR + rs] = v.w;
    }
    if (tid < TR) sq1s[tid] = g_sq1[row0 + tid];

    float minv[8];
    #pragma unroll
    for (int i = 0; i < 8; i++) minv[i] = 1e30f;

    const float4* o2v = (const float4*)o2;

    // this thread's fixed slice of each B tile: 8 float4s
    int pq = tid & 15;        // float4 index along D
    int pr = tid >> 4;        // base row (stride 16 over i)
    int prs_base = 0;         // recomputed per store

    // prefetch tile 0
    float4 pv[8];
    float psq2;
    {
        int col0 = cb * COLS_PER;
        #pragma unroll
        for (int i = 0; i < 8; i++)
            pv[i] = o2v[(col0 + pr + i * 16) * (DDIM / 4) + pq];
        psq2 = (tid < TC) ? g_sq2[col0 + tid] : 0.0f;
    }

    for (int ct = 0; ct < NTILES; ct++) {
        __syncthreads();  // previous compute done before Bs overwrite
        // store prefetched tile into smem (transpose + swizzle)
        {
            int k = pq * 4;
            #pragma unroll
            for (int i = 0; i < 8; i++) {
                int r = pr + i * 16;
                int rs = r ^ ((pq & 7) << 2);
                Bs[(k + 0) * TC + rs] = pv[i].x;
                Bs[(k + 1) * TC + rs] = pv[i].y;
                Bs[(k + 2) * TC + rs] = pv[i].z;
                Bs[(k + 3) * TC + rs] = pv[i].w;
            }
            if (tid < TC) sq2s[tid] = psq2;
        }
        __syncthreads();

        // issue prefetch of NEXT tile; LDGs retire during compute below
        if (ct + 1 < NTILES) {
            int coln = cb * COLS_PER + (ct + 1) * TC;
            #pragma unroll
            for (int i = 0; i < 8; i++)
                pv[i] = o2v[(coln + pr + i * 16) * (DDIM / 4) + pq];
            psq2 = (tid < TC) ? g_sq2[coln + tid] : 0.0f;
        }

        // packed accumulators: accp[r][c4] holds columns (2*c4, 2*c4+1)
        unsigned long long accp[8][4];
        #pragma unroll
        for (int r = 0; r < 8; r++)
            #pragma unroll
            for (int c = 0; c < 4; c++) accp[r][c] = 0ULL;

        #pragma unroll 8
        for (int k = 0; k < DDIM; k++) {
            int sw = ((k >> 2) & 7) << 2;
            float4 a0 = *(const float4*)&As[k * TR + ((ty * 8) ^ sw)];
            float4 a1 = *(const float4*)&As[k * TR + ((ty * 8 + 4) ^ sw)];
            ulonglong2 t0 = *(const ulonglong2*)&Bs[k * TC + ((tx * 8) ^ sw)];
            ulonglong2 t1 = *(const ulonglong2*)&Bs[k * TC + ((tx * 8 + 4) ^ sw)];
            unsigned long long bp[4] = {t0.x, t0.y, t1.x, t1.y};
            float ar[8] = {a0.x, a0.y, a0.z, a0.w, a1.x, a1.y, a1.z, a1.w};
            #pragma unroll
            for (int r = 0; r < 8; r++) {
                unsigned long long aa;
                asm("mov.b64 %0, {%1, %1};" : "=l"(aa) : "f"(ar[r]));
                #pragma unroll
                for (int c = 0; c < 4; c++) {
                    asm("fma.rn.f32x2 %0, %1, %2, %3;"
                        : "=l"(accp[r][c])
                        : "l"(aa), "l"(bp[c]), "l"(accp[r][c]));
                }
            }
        }

        // epilogue: d2 = sq1 + sq2 - 2*dot ; track per-row min
        #pragma unroll
        for (int r = 0; r < 8; r++) {
            float s1 = sq1s[ty * 8 + r];
            #pragma unroll
            for (int c = 0; c < 4; c++) {
                unsigned int ulo, uhi;
                asm("mov.b64 {%0, %1}, %2;" : "=r"(ulo), "=r"(uhi) : "l"(accp[r][c]));
                float dlo = __uint_as_float(ulo);
                float dhi = __uint_as_float(uhi);
                float d2a = fmaf(-2.0f, dlo, s1 + sq2s[tx * 8 + 2 * c]);
                float d2b = fmaf(-2.0f, dhi, s1 + sq2s[tx * 8 + 2 * c + 1]);
                minv[r] = fminf(minv[r], fminf(d2a, d2b));
            }
        }
    }

    // cross-thread per-row min reduction (reuse As)
    __syncthreads();
    float* red = As;  // [TR][16]
    #pragma unroll
    for (int r = 0; r < 8; r++) red[(ty * 8 + r) * 16 + tx] = minv[r];
    __syncthreads();
    if (tid < TR) {
        float m = red[tid * 16];
        #pragma unroll
        for (int j = 1; j < 16; j++) m = fminf(m, red[tid * 16 + j]);
        g_minpart[cb][row0 + tid] = m;
    }
    (void)prs_base;
}

// ---------------------------------------------------------------- exact fallback
// grid 64, block 256. Processes only rows whose min d2 < THRESH (expected: none).
__global__ void exact_kernel(const float* __restrict__ o1,
                             const float* __restrict__ o2,
                             const int* __restrict__ rn,
                             const int* __restrict__ quant_p) {
    __shared__ float qv[DDIM];
    __shared__ unsigned long long sred[256];
    __shared__ float svals[1024];
    __shared__ int   sidx[1024];
    int tid = threadIdx.x;

    int quant = quant_p ? quant_p[0] : 100;
    int q = quant < (NROWS - 1) ? quant : (NROWS - 1);
    if (q > 1024) q = 1024;
    if (q < 1) q = 1;

    for (int row = blockIdx.x; row < NROWS; row += gridDim.x) {
        float m = fminf(g_minpart[0][row], g_minpart[1][row]);
        if (m >= THRESH) continue;   // block-uniform condition

        if (tid < DDIM) qv[tid] = o1[row * DDIM + tid];
        __syncthreads();

        unsigned long long* keys = g_scratch[blockIdx.x];
        float s1 = g_sq1[row];
        for (int j = tid; j < NROWS; j += 256) {
            float dot = 0.0f;
            #pragma unroll 8
            for (int d = 0; d < DDIM; d++) dot = fmaf(qv[d], o2[j * DDIM + d], dot);
            float d2 = fmaxf(fmaf(-2.0f, dot, s1 + g_sq2[j]), 0.0f);
            keys[j] = ((unsigned long long)__float_as_uint(d2) << 32) |
                      (unsigned long long)(unsigned)j;
        }
        __syncthreads();

        // q iterations of argmin (value, then lowest index: matches lax.top_k ties)
        for (int kk = 0; kk < q; kk++) {
            unsigned long long best = ~0ULL;
            for (int j = tid; j < NROWS; j += 256) {
                unsigned long long v = keys[j];
                if (v < best) best = v;
            }
            sred[tid] = best;
            __syncthreads();
            for (int s = 128; s > 0; s >>= 1) {
                if (tid < s && sred[tid + s] < sred[tid]) sred[tid] = sred[tid + s];
                __syncthreads();
            }
            if (tid == 0) {
                unsigned long long b = sred[0];
                int bj = (int)(unsigned)(b & 0xFFFFFFFFULL);
                float d2 = __uint_as_float((unsigned)(b >> 32));
                svals[kk] = (d2 > 0.0f) ? sqrtf(d2) : 0.0f;
                sidx[kk]  = bj;
                keys[bj] = ~0ULL;
            }
            __syncthreads();
        }

        if (tid == 0) {
            int k = rn[row];
            k = ((k % q) + q) % q;
            if (sidx[k] == row) k = (k + 1) % q;
            float neg = MARGIN_V - svals[k];
            g_neg[row] = neg > 0.0f ? neg : 0.0f;
        }
        __syncthreads();
    }
}

// ---------------------------------------------------------------- finalize
__global__ void finalize_kernel(float* __restrict__ out) {
    __shared__ float s[256];
    int tid = threadIdx.x;
    float acc = 0.0f;
    for (int i = tid; i < NROWS; i += 256) acc += g_pos[i] + g_neg[i];
    s[tid] = acc;
    __syncthreads();
    for (int off = 128; off > 0; off >>= 1) {
        if (tid < off) s[tid] += s[tid + off];
        __syncthreads();
    }
    if (tid == 0) out[0] = s[0] / (float)NROWS;
}

// ---------------------------------------------------------------- launch
extern "C" void kernel_launch(void* const* d_in, const int* in_sizes, int n_in,
                              void* d_out, int out_size) {
    const float* o1 = (const float*)d_in[0];
    const float* o2 = (const float*)d_in[1];
    const int* rn   = (const int*)d_in[2];
    const int* quant = (n_in >= 4) ? (const int*)d_in[3] : nullptr;
    float* out = (float*)d_out;

    init_kernel<<<(NROWS + 255) / 256, 256>>>();
    norms_kernel<<<NROWS / 8, 256>>>(o1, o2);
    screen_kernel<<<dim3(NROWS / TR, NCTA_COL), 256>>>(o1, o2);
    exact_kernel<<<64, 256>>>(o1, o2, rn, quant);
    finalize_kernel<<<1, 256>>>(out);
}

// round 6
// speedup vs baseline: 2.0426x; 2.0426x over previous
#include <cuda_runtime.h>
#include <cuda_bf16.h>
#include <math.h>

// SimilarityLoss: out = mean(pos) + mean(clip(MARGIN - kth-smallest-dist, 0))
//   norms    : fused init (g_neg=0, g_mind2=+inf, g_nflag=0) + per-row full
//              and partial(first 32 dims) sq norms + positive loss
//   screen   : fp32 GEMM over FIRST 32 DIMS ONLY (lower bound on d2:
//              d2_64 >= d2_32, so rows with true d2 < 4 are always flagged).
//              packed fma.rn.f32x2 + register prefetch; per-row min via
//              atomicMin on ordered-uint bits (deterministic).
//   compact  : list of rows with min d2_32 < 4.5 (expected: none)
//   exact    : flagged rows only, full-precision top-quant with jax-top_k
//              tie-breaking; reads flag count once, exits if 0
//   finalize : deterministic fixed-order reduction -> scalar

#define NROWS 8192
#define DDIM  64
#define KSCR  32           // screen dims (lower-bound subset)
#define TR    128          // row tile
#define TC    128          // col tile
#define NCTA_COL 2         // column split -> 64*2 = 128 CTAs
#define COLS_PER (NROWS / NCTA_COL)
#define NTILES   (COLS_PER / TC)
#define THRESH   4.5f      // screen threshold on d2 (exact boundary is 4.0)
#define MARGIN_V 2.0f

__device__ float g_sq1[NROWS];    // full norms (exact path)
__device__ float g_sq2[NROWS];
__device__ float g_sq1p[NROWS];   // partial norms over dims [0,32) (screen)
__device__ float g_sq2p[NROWS];
__device__ float g_pos[NROWS];
__device__ float g_neg[NROWS];
__device__ unsigned int g_mind2[NROWS];
__device__ int g_flagged[NROWS];
__device__ int g_nflag;
__device__ unsigned long long g_scratch[64][NROWS];  // exact-path keys (4MB)

// ---------------------------------------------------------------- norms + pos + init
__global__ void norms_kernel(const float* __restrict__ o1,
                             const float* __restrict__ o2) {
    int warp = threadIdx.x >> 5;
    int lane = threadIdx.x & 31;
    int row = blockIdx.x * 8 + warp;
    if (row >= NROWS) return;
    if (threadIdx.x == 0 && blockIdx.x == 0) g_nflag = 0;
    const float* a = o1 + row * DDIM;
    const float* b = o2 + row * DDIM;
    float a0 = a[lane], a1 = a[lane + 32];   // a0: dims [0,32)
    float b0 = b[lane], b1 = b[lane + 32];
    float s1p = a0 * a0;
    float s2p = b0 * b0;
    float s1 = s1p + a1 * a1;
    float s2 = s2p + b1 * b1;
    float d0 = b0 - a0, d1 = b1 - a1;
    float pp = d0 * d0 + d1 * d1;
    #pragma unroll
    for (int off = 16; off > 0; off >>= 1) {
        s1  += __shfl_xor_sync(0xffffffffu, s1,  off);
        s2  += __shfl_xor_sync(0xffffffffu, s2,  off);
        s1p += __shfl_xor_sync(0xffffffffu, s1p, off);
        s2p += __shfl_xor_sync(0xffffffffu, s2p, off);
        pp  += __shfl_xor_sync(0xffffffffu, pp,  off);
    }
    if (lane == 0) {
        g_sq1[row] = s1;
        g_sq2[row] = s2;
        g_sq1p[row] = s1p;
        g_sq2p[row] = s2p;
        g_pos[row] = pp;
        g_neg[row] = 0.0f;
        g_mind2[row] = 0x7F800000u;  // +inf
    }
}

// ---------------------------------------------------------------- screen GEMM
// grid (64, 2), block 256. Each CTA: 128 rows x 4096 cols, K=32 (dims [0,32)).
// smem tiles k-major with XOR swizzle: idx = k*128 + (r ^ (((k>>2)&7)<<2)).
// Packed fma.rn.f32x2 inner product; next B tile register-prefetched.
__global__ void __launch_bounds__(256, 1)
screen_kernel(const float* __restrict__ o1, const float* __restrict__ o2) {
    __shared__ float As[KSCR * TR];
    __shared__ float Bs[KSCR * TC];
    __shared__ float sq1s[TR];
    __shared__ float sq2s[TC];

    int tid = threadIdx.x;
    int tx = tid & 15;        // 16 col groups of 8
    int ty = tid >> 4;        // 16 row groups of 8
    int row0 = blockIdx.x * TR;
    int cb = blockIdx.y;

    // load A tile once: first 32 dims of 128 rows
    const float4* o1v = (const float4*)o1;
    #pragma unroll
    for (int i = 0; i < 4; i++) {
        int idx = tid + i * 256;          // 0..1023
        int q = idx & 7;                  // float4 index within dims [0,32)
        int r = idx >> 3;                 // row within tile
        float4 v = o1v[(row0 + r) * (DDIM / 4) + q];
        int k = q * 4;
        int rs = r ^ (q << 2);
        As[(k + 0) * TR + rs] = v.x;
        As[(k + 1) * TR + rs] = v.y;
        As[(k + 2) * TR + rs] = v.z;
        As[(k + 3) * TR + rs] = v.w;
    }
    if (tid < TR) sq1s[tid] = g_sq1p[row0 + tid];

    float minv[8];
    #pragma unroll
    for (int i = 0; i < 8; i++) minv[i] = 1e30f;

    const float4* o2v = (const float4*)o2;

    // this thread's fixed slice of each B tile: 4 float4s
    int pq = tid & 7;         // float4 index within dims [0,32)
    int pr = tid >> 3;        // base row 0..31 (stride 32 over i)

    // prefetch tile 0
    float4 pv[4];
    float psq2;
    {
        int col0 = cb * COLS_PER;
        #pragma unroll
        for (int i = 0; i < 4; i++)
            pv[i] = o2v[(col0 + pr + i * 32) * (DDIM / 4) + pq];
        psq2 = (tid < TC) ? g_sq2p[col0 + tid] : 0.0f;
    }

    for (int ct = 0; ct < NTILES; ct++) {
        __syncthreads();  // previous compute done before Bs overwrite
        {
            int k = pq * 4;
            #pragma unroll
            for (int i = 0; i < 4; i++) {
                int r = pr + i * 32;
                int rs = r ^ (pq << 2);
                Bs[(k + 0) * TC + rs] = pv[i].x;
                Bs[(k + 1) * TC + rs] = pv[i].y;
                Bs[(k + 2) * TC + rs] = pv[i].z;
                Bs[(k + 3) * TC + rs] = pv[i].w;
            }
            if (tid < TC) sq2s[tid] = psq2;
        }
        __syncthreads();

        // prefetch NEXT tile; LDGs retire during compute below
        if (ct + 1 < NTILES) {
            int coln = cb * COLS_PER + (ct + 1) * TC;
            #pragma unroll
            for (int i = 0; i < 4; i++)
                pv[i] = o2v[(coln + pr + i * 32) * (DDIM / 4) + pq];
            psq2 = (tid < TC) ? g_sq2p[coln + tid] : 0.0f;
        }

        // packed accumulators: accp[r][c4] holds columns (2*c4, 2*c4+1)
        unsigned long long accp[8][4];
        #pragma unroll
        for (int r = 0; r < 8; r++)
            #pragma unroll
            for (int c = 0; c < 4; c++) accp[r][c] = 0ULL;

        #pragma unroll 8
        for (int k = 0; k < KSCR; k++) {
            int sw = ((k >> 2) & 7) << 2;
            float4 a0 = *(const float4*)&As[k * TR + ((ty * 8) ^ sw)];
            float4 a1 = *(const float4*)&As[k * TR + ((ty * 8 + 4) ^ sw)];
            ulonglong2 t0 = *(const ulonglong2*)&Bs[k * TC + ((tx * 8) ^ sw)];
            ulonglong2 t1 = *(const ulonglong2*)&Bs[k * TC + ((tx * 8 + 4) ^ sw)];
            unsigned long long bp[4] = {t0.x, t0.y, t1.x, t1.y};
            float ar[8] = {a0.x, a0.y, a0.z, a0.w, a1.x, a1.y, a1.z, a1.w};
            #pragma unroll
            for (int r = 0; r < 8; r++) {
                unsigned long long aa;
                asm("mov.b64 %0, {%1, %1};" : "=l"(aa) : "f"(ar[r]));
                #pragma unroll
                for (int c = 0; c < 4; c++) {
                    asm("fma.rn.f32x2 %0, %1, %2, %3;"
                        : "=l"(accp[r][c])
                        : "l"(aa), "l"(bp[c]), "l"(accp[r][c]));
                }
            }
        }

        // epilogue: d2_32 = s1p + s2p - 2*dot ; track per-row min
        #pragma unroll
        for (int r = 0; r < 8; r++) {
            float s1 = sq1s[ty * 8 + r];
            #pragma unroll
            for (int c = 0; c < 4; c++) {
                unsigned int ulo, uhi;
                asm("mov.b64 {%0, %1}, %2;" : "=r"(ulo), "=r"(uhi) : "l"(accp[r][c]));
                float dlo = __uint_as_float(ulo);
                float dhi = __uint_as_float(uhi);
                float d2a = fmaf(-2.0f, dlo, s1 + sq2s[tx * 8 + 2 * c]);
                float d2b = fmaf(-2.0f, dhi, s1 + sq2s[tx * 8 + 2 * c + 1]);
                minv[r] = fminf(minv[r], fminf(d2a, d2b));
            }
        }
    }

    // cross-thread per-row min reduction (reuse As)
    __syncthreads();
    float* red = As;  // [TR][16] = 2048 floats, fits in As (4096)
    #pragma unroll
    for (int r = 0; r < 8; r++) red[(ty * 8 + r) * 16 + tx] = minv[r];
    __syncthreads();
    if (tid < TR) {
        float m = red[tid * 16];
        #pragma unroll
        for (int j = 1; j < 16; j++) m = fminf(m, red[tid * 16 + j]);
        m = fmaxf(m, 0.0f);  // keep uint ordering monotonic
        atomicMin(&g_mind2[row0 + tid], __float_as_uint(m));
    }
}

// ---------------------------------------------------------------- compact
__global__ void compact_kernel() {
    int row = blockIdx.x * blockDim.x + threadIdx.x;
    bool flag = false;
    if (row < NROWS)
        flag = __uint_as_float(g_mind2[row]) < THRESH;
    unsigned int ball = __ballot_sync(0xffffffffu, flag);
    int lane = threadIdx.x & 31;
    if (ball != 0) {
        int base = 0;
        if (lane == 0) base = atomicAdd(&g_nflag, __popc(ball));
        base = __shfl_sync(0xffffffffu, base, 0);
        if (flag) {
            int off = __popc(ball & ((1u << lane) - 1u));
            g_flagged[base + off] = row;
        }
    }
}

// ---------------------------------------------------------------- exact fallback
// grid 64, block 256. Processes only flagged rows (expected count: 0).
// Full-precision 64-dim math; independent of the screen's subset trick.
__global__ void exact_kernel(const float* __restrict__ o1,
                             const float* __restrict__ o2,
                             const int* __restrict__ rn,
                             const int* __restrict__ quant_p) {
    __shared__ float qv[DDIM];
    __shared__ unsigned long long sred[256];
    __shared__ float svals[1024];
    __shared__ int   sidx[1024];
    int tid = threadIdx.x;

    int nflag = g_nflag;
    if (nflag == 0) return;

    int quant = quant_p ? quant_p[0] : 100;
    int q = quant < (NROWS - 1) ? quant : (NROWS - 1);
    if (q > 1024) q = 1024;
    if (q < 1) q = 1;

    for (int fi = blockIdx.x; fi < nflag; fi += gridDim.x) {
        int row = g_flagged[fi];

        if (tid < DDIM) qv[tid] = o1[row * DDIM + tid];
        __syncthreads();

        unsigned long long* keys = g_scratch[blockIdx.x];
        float s1 = g_sq1[row];
        for (int j = tid; j < NROWS; j += 256) {
            float dot = 0.0f;
            #pragma unroll 8
            for (int d = 0; d < DDIM; d++) dot = fmaf(qv[d], o2[j * DDIM + d], dot);
            float d2 = fmaxf(fmaf(-2.0f, dot, s1 + g_sq2[j]), 0.0f);
            keys[j] = ((unsigned long long)__float_as_uint(d2) << 32) |
                      (unsigned long long)(unsigned)j;
        }
        __syncthreads();

        // q iterations of argmin (value, then lowest index: matches lax.top_k)
        for (int kk = 0; kk < q; kk++) {
            unsigned long long best = ~0ULL;
            for (int j = tid; j < NROWS; j += 256) {
                unsigned long long v = keys[j];
                if (v < best) best = v;
            }
            sred[tid] = best;
            __syncthreads();
            for (int s = 128; s > 0; s >>= 1) {
                if (tid < s && sred[tid + s] < sred[tid]) sred[tid] = sred[tid + s];
                __syncthreads();
            }
            if (tid == 0) {
                unsigned long long b = sred[0];
                int bj = (int)(unsigned)(b & 0xFFFFFFFFULL);
                float d2 = __uint_as_float((unsigned)(b >> 32));
                svals[kk] = (d2 > 0.0f) ? sqrtf(d2) : 0.0f;
                sidx[kk]  = bj;
                keys[bj] = ~0ULL;
            }
            __syncthreads();
        }

        if (tid == 0) {
            int k = rn[row];
            k = ((k % q) + q) % q;
            if (sidx[k] == row) k = (k + 1) % q;
            float neg = MARGIN_V - svals[k];
            g_neg[row] = neg > 0.0f ? neg : 0.0f;
        }
        __syncthreads();
    }
}

// ---------------------------------------------------------------- finalize
__global__ void finalize_kernel(float* __restrict__ out) {
    __shared__ float s[256];
    int tid = threadIdx.x;
    const float4* p4 = (const float4*)g_pos;
    const float4* n4 = (const float4*)g_neg;
    float acc = 0.0f;
    for (int i = tid; i < NROWS / 4; i += 256) {
        float4 p = p4[i];
        float4 n = n4[i];
        acc += ((p.x + p.y) + (p.z + p.w)) + ((n.x + n.y) + (n.z + n.w));
    }
    s[tid] = acc;
    __syncthreads();
    for (int off = 128; off > 0; off >>= 1) {
        if (tid < off) s[tid] += s[tid + off];
        __syncthreads();
    }
    if (tid == 0) out[0] = s[0] / (float)NROWS;
}

// ---------------------------------------------------------------- launch
extern "C" void kernel_launch(void* const* d_in, const int* in_sizes, int n_in,
                              void* d_out, int out_size) {
    const float* o1 = (const float*)d_in[0];
    const float* o2 = (const float*)d_in[1];
    const int* rn   = (const int*)d_in[2];
    const int* quant = (n_in >= 4) ? (const int*)d_in[3] : nullptr;
    float* out = (float*)d_out;

    norms_kernel<<<NROWS / 8, 256>>>(o1, o2);
    screen_kernel<<<dim3(NROWS / TR, NCTA_COL), 256>>>(o1, o2);
    compact_kernel<<<NROWS / 256, 256>>>();
    exact_kernel<<<64, 256>>>(o1, o2, rn, quant);
    finalize_kernel<<<1, 256>>>(out);
}